// round 9
// baseline (speedup 1.0000x reference)
#include <cuda_runtime.h>
#include <math.h>

#define HW 192
#define NPIX (HW*HW)
#define NB 2
#define CIN 180
#define CP 360
#define KDIM 180

#define PROJ_GRID_X 288
#define PROJ_GRID_Y 3
#define PROJ_BLOCKS_PER_B (PROJ_GRID_X*PROJ_GRID_Y)

// ---------------- scratch (static device globals; no allocation) ----------------
__device__ float g_xp[(size_t)NB*CP*NPIX];     // projected (pre-GN) features, 106 MB
__device__ float g_yf[(size_t)NB*CIN*NPIX];    // fused attention output, 53 MB
__device__ float g_part[NB*PROJ_BLOCKS_PER_B*4];
__device__ float g_stats[8];                   // [b][g] -> {mu, inv_std}
__device__ float g_affA[NB*CP];                // folded GN scale per (b, channel)
__device__ float g_affB[NB*CP];                // folded GN bias  per (b, channel)

// ---------------- SGEMM: C[b] = W (MxK) @ X[b] (KxNPIX) + bias ----------------
// BM=BN=128, BK=8, 256 threads, 8x8 register tile per thread.
// PROJ=true : X = input x, C = g_xp, also emit GroupNorm partial sums.
// PROJ=false: X = g_yf,   C = d_out (y).
template<bool PROJ>
__global__ void __launch_bounds__(256) gemm_kernel(const float* __restrict__ W, int M,
                                                   const float* __restrict__ Xin,
                                                   const float* __restrict__ bias,
                                                   float* __restrict__ Cout)
{
  __shared__ float smem[2048];
  float* As = smem;          // [8][128]  (k-major)
  float* Bs = smem + 1024;   // [8][128]
  const int b = blockIdx.z;
  const float* X = PROJ ? (Xin + (size_t)b*KDIM*NPIX)
                        : (g_yf + (size_t)b*CIN*NPIX);
  float* C = PROJ ? (g_xp + (size_t)b*CP*NPIX)
                  : (Cout + (size_t)b*CIN*NPIX);
  const int tid = threadIdx.x;
  const int tc = tid & 15, tr = tid >> 4;
  const int m0 = blockIdx.y*128, n0 = blockIdx.x*128;

  float acc[8][8];
#pragma unroll
  for (int i=0;i<8;i++)
#pragma unroll
    for (int j=0;j<8;j++) acc[i][j] = 0.f;

  for (int k0 = 0; k0 < KDIM; k0 += 8){
#pragma unroll
    for (int l=0;l<4;l++){
      int idx = tid + l*256;
      int k = idx & 7, m = idx >> 3;
      int gm = m0 + m, gk = k0 + k;
      As[k*128 + m] = (gm < M && gk < KDIM) ? W[gm*KDIM + gk] : 0.f;
    }
#pragma unroll
    for (int l=0;l<4;l++){
      int idx = tid + l*256;
      int k = idx >> 7, n = idx & 127;
      int gk = k0 + k;
      Bs[k*128 + n] = (gk < KDIM) ? X[(size_t)gk*NPIX + n0 + n] : 0.f;
    }
    __syncthreads();
#pragma unroll
    for (int k=0;k<8;k++){
      float4 a0 = *(const float4*)(As + k*128 + tr*4);
      float4 a1 = *(const float4*)(As + k*128 + 64 + tr*4);
      float4 b0 = *(const float4*)(Bs + k*128 + tc*4);
      float4 b1 = *(const float4*)(Bs + k*128 + 64 + tc*4);
      float av[8] = {a0.x,a0.y,a0.z,a0.w,a1.x,a1.y,a1.z,a1.w};
      float bv[8] = {b0.x,b0.y,b0.z,b0.w,b1.x,b1.y,b1.z,b1.w};
#pragma unroll
      for (int i=0;i<8;i++)
#pragma unroll
        for (int j=0;j<8;j++)
          acc[i][j] = fmaf(av[i], bv[j], acc[i][j]);
    }
    __syncthreads();
  }

  float st0=0.f, st1=0.f, st2=0.f, st3=0.f;
#pragma unroll
  for (int ih=0; ih<2; ih++){
#pragma unroll
    for (int i=0;i<4;i++){
      int gm = m0 + ih*64 + tr*4 + i;
      if (gm < M){
        float bb = bias[gm];
        float r[8];
#pragma unroll
        for (int j=0;j<8;j++) r[j] = acc[ih*4+i][j] + bb;
        float* crow = C + (size_t)gm*NPIX + n0;
        *(float4*)(crow + tc*4)      = make_float4(r[0],r[1],r[2],r[3]);
        *(float4*)(crow + 64 + tc*4) = make_float4(r[4],r[5],r[6],r[7]);
        if (PROJ){
          float s = 0.f, q = 0.f;
#pragma unroll
          for (int j=0;j<8;j++){ s += r[j]; q = fmaf(r[j], r[j], q); }
          if (gm < CIN){ st0 += s; st1 += q; } else { st2 += s; st3 += q; }
        }
      }
    }
  }
  if (PROJ){
    __syncthreads();
    smem[tid] = st0; smem[256+tid] = st1; smem[512+tid] = st2; smem[768+tid] = st3;
    __syncthreads();
    for (int o=128;o;o>>=1){
      if (tid < o){
        smem[tid]     += smem[tid+o];
        smem[256+tid] += smem[256+tid+o];
        smem[512+tid] += smem[512+tid+o];
        smem[768+tid] += smem[768+tid+o];
      }
      __syncthreads();
    }
    if (tid == 0){
      int bid = (blockIdx.z*gridDim.y + blockIdx.y)*gridDim.x + blockIdx.x;
      g_part[bid*4+0]=smem[0];   g_part[bid*4+1]=smem[256];
      g_part[bid*4+2]=smem[512]; g_part[bid*4+3]=smem[768];
    }
  }
}

// ---------------- GroupNorm stats: deterministic reduce of partials ----------------
__global__ void stats_kernel()
{
  const int bg = blockIdx.x;          // b*2 + g, 4 blocks
  const int b = bg >> 1, g = bg & 1;
  __shared__ float ss[256], sq[256];
  float s = 0.f, q = 0.f;
  for (int i = threadIdx.x; i < PROJ_BLOCKS_PER_B; i += 256){
    int bid = b*PROJ_BLOCKS_PER_B + i;
    s += g_part[bid*4 + g*2];
    q += g_part[bid*4 + g*2 + 1];
  }
  ss[threadIdx.x] = s; sq[threadIdx.x] = q;
  __syncthreads();
  for (int o=128;o;o>>=1){
    if (threadIdx.x < o){ ss[threadIdx.x]+=ss[threadIdx.x+o]; sq[threadIdx.x]+=sq[threadIdx.x+o]; }
    __syncthreads();
  }
  if (threadIdx.x == 0){
    const float N = 180.f * (float)NPIX;
    float mu  = ss[0] / N;
    float var = sq[0] / N - mu*mu;
    g_stats[bg*2]   = mu;
    g_stats[bg*2+1] = rsqrtf(var + 1e-5f);
  }
}

// Fold GN into per-(batch,channel) affine: xn = xp * A + B
__global__ void affine_kernel(const float* __restrict__ gamma, const float* __restrict__ beta)
{
  int i = blockIdx.x*256 + threadIdx.x;
  if (i < NB*CP){
    int c = i % CP, b = i / CP;
    int g = (c >= CIN) ? 1 : 0;
    float mu   = g_stats[(b*2+g)*2];
    float istd = g_stats[(b*2+g)*2+1];
    float a = istd * gamma[c];
    g_affA[i] = a;
    g_affB[i] = fmaf(-mu, a, beta[c]);
  }
}

// ---------------- windowed attention, one block per (window, head) ----------------
// NOTE: the reference's "global token" path is an exact identity
// (softmax of selected rows == selected rows of softmax), so attn maps and
// outputs are the plain local window attention.
// Writes softmax rows to attn_out (= d_out slice) and scale_w * (attn@V)
// directly into g_yf (branch channel block of 60, inner channel cc*HE+hh).
template<int WS, int HE, int CHN, int NCH>
__global__ void __launch_bounds__(256) attn_kernel(int branch,
                                                   const float* __restrict__ swp,
                                                   float* __restrict__ attn_out)
{
  constexpr int T    = WS*WS;
  constexpr int NWIN = HW/WS;
  constexpr int TPAD = T + 4;
  constexpr int CPC  = CHN / NCH;
  static_assert(CHN % NCH == 0, "chunking");

  extern __shared__ float sm[];
  float* qT = sm;                  // [CHN][T]  (already *he^-0.5, GN applied)
  float* vT = sm + CHN*T;          // [CHN][T]
  float* Am = sm + 2*CHN*T;        // [T][TPAD]
  __shared__ int pixs[T];

  const int w  = blockIdx.x;
  const int hh = blockIdx.y;
  const int b  = w / (NWIN*NWIN);
  const int r  = w - b*NWIN*NWIN;
  const int ih = r / NWIN, iw = r - ih*NWIN;
  const int tid = threadIdx.x;

  if (tid < T){
    int ty = tid / WS, tx = tid - ty*WS;
    int hs  = (ih*WS + ty - WS/2 + HW) % HW;   // roll(+ws/2) on H
    int wsr = (iw*WS + tx + WS/2) % HW;        // roll(-ws/2) on W
    pixs[tid] = hs*HW + wsr;                   // same pixel for gather & scatter
  }
  __syncthreads();

  const float qsc = (HE==2) ? 0.70710678f : (HE==4) ? 0.5f : 0.40824829f;
  const float* xp = g_xp + (size_t)b*CP*NPIX;
  const float* aA = g_affA + b*CP;
  const float* aB = g_affB + b*CP;
  const int cb = branch*120 + hh;             // q channel = cb + cc*HE ; v = +60

  // ---- load + GN-normalize Q,V ----
  for (int idx = tid; idx < CHN*T; idx += 256){
    int cc = idx / T, t = idx - cc*T;
    int pix = pixs[t];
    int Cq = cb + cc*HE;
    int Cv = Cq + 60;
    float q = xp[(size_t)Cq*NPIX + pix];
    float v = xp[(size_t)Cv*NPIX + pix];
    qT[idx] = fmaf(q, aA[Cq], aB[Cq]) * qsc;
    vT[idx] = fmaf(v, aA[Cv], aB[Cv]);
  }
  __syncthreads();

  // ---- S = (q_l)(q_l)^T  (4x4 register tiles) ----
  constexpr int NT4 = T/4;
  for (int tile = tid; tile < NT4*NT4; tile += 256){
    int tt = tile / NT4, ssi = tile - tt*NT4;
    int t0 = tt*4, s0 = ssi*4;
    float accv[4][4];
#pragma unroll
    for (int i=0;i<4;i++)
#pragma unroll
      for (int j=0;j<4;j++) accv[i][j] = 0.f;
#pragma unroll
    for (int c=0;c<CHN;c++){
      float4 qa = *(const float4*)(qT + c*T + t0);
      float4 qb = *(const float4*)(qT + c*T + s0);
      float qav[4] = {qa.x,qa.y,qa.z,qa.w};
      float qbv[4] = {qb.x,qb.y,qb.z,qb.w};
#pragma unroll
      for (int i=0;i<4;i++)
#pragma unroll
        for (int j=0;j<4;j++)
          accv[i][j] = fmaf(qav[i], qbv[j], accv[i][j]);
    }
#pragma unroll
    for (int i=0;i<4;i++)
      *(float4*)(Am + (t0+i)*TPAD + s0) =
          make_float4(accv[i][0],accv[i][1],accv[i][2],accv[i][3]);
  }
  __syncthreads();

  // ---- softmax per row + write attn map to global ----
  const int warp = tid >> 5, lane = tid & 31;
  for (int t = warp; t < T; t += 8){
    float* arow = Am + t*TPAD;
    float mx = -1e30f;
    for (int s=lane; s<T; s+=32) mx = fmaxf(mx, arow[s]);
#pragma unroll
    for (int o=16;o;o>>=1) mx = fmaxf(mx, __shfl_xor_sync(0xffffffffu, mx, o));
    float sum = 0.f;
    for (int s=lane; s<T; s+=32){ float e = __expf(arow[s]-mx); arow[s]=e; sum+=e; }
#pragma unroll
    for (int o=16;o;o>>=1) sum += __shfl_xor_sync(0xffffffffu, sum, o);
    float inv = 1.f/sum;
    float* grow = attn_out + (((size_t)w*HE + hh)*T + t)*T;
    for (int s=lane; s<T; s+=32){ float p = arow[s]*inv; arow[s]=p; grow[s]=p; }
  }
  __syncthreads();

  // ---- O = attn @ V, scatter scaled output into y_fused ----
  float sw = swp[branch];
  if (tid < T*NCH){
    int chunk = tid / T, t = tid - chunk*T;
    const float* arow = Am + t*TPAD;
    const float* vb = vT + chunk*CPC*T;
    float o[CPC];
#pragma unroll
    for (int c=0;c<CPC;c++) o[c] = 0.f;
    for (int s=0; s<T; s+=4){
      float4 a4 = *(const float4*)(arow + s);
#pragma unroll
      for (int c=0;c<CPC;c++){
        float4 v4 = *(const float4*)(vb + c*T + s);
        o[c] = fmaf(a4.x, v4.x, o[c]);
        o[c] = fmaf(a4.y, v4.y, o[c]);
        o[c] = fmaf(a4.z, v4.z, o[c]);
        o[c] = fmaf(a4.w, v4.w, o[c]);
      }
    }
    int pix = pixs[t];
    float* yb = g_yf + (size_t)b*CIN*NPIX;
#pragma unroll
    for (int c=0;c<CPC;c++){
      int cc = chunk*CPC + c;
      int Cy = branch*60 + cc*HE + hh;
      yb[(size_t)Cy*NPIX + pix] = sw * o[c];
    }
  }
}

// ---------------- launcher ----------------
extern "C" void kernel_launch(void* const* d_in, const int* in_sizes, int n_in,
                              void* d_out, int out_size)
{
  const float* x        = (const float*)d_in[0];
  const float* proj_w   = (const float*)d_in[1];
  const float* proj_b   = (const float*)d_in[2];
  const float* gn_gamma = (const float*)d_in[3];
  const float* gn_beta  = (const float*)d_in[4];
  // d_in[5] token_scores: provably unused (global path is identity)
  const float* scale_w  = (const float*)d_in[6];
  const float* fuse_w   = (const float*)d_in[7];
  const float* fuse_b   = (const float*)d_in[8];
  float* out = (float*)d_out;

  // d_out layout: y | atn0 | atn1 | atn2
  const size_t OFF_A0 = (size_t)NB*CIN*NPIX;                 // 13,271,040
  const size_t OFF_A1 = OFF_A0 + (size_t)NB*48*48*2*16*16;   // +2,359,296
  const size_t OFF_A2 = OFF_A1 + (size_t)NB*24*24*4*64*64;   // +18,874,368

  // branch-2 attention needs ~94.5 KB dynamic smem
  const int SM0 = (2*30*16  + 16*20)  * 4;   //  5,120 B
  const int SM1 = (2*15*64  + 64*68)  * 4;   // 25,088 B
  const int SM2 = (2*10*144 + 144*148)* 4;   // 96,768 B
  cudaFuncSetAttribute(attn_kernel<12,6,10,1>,
                       cudaFuncAttributeMaxDynamicSharedMemorySize, SM2);

  // 1) proj GEMM + GN partials
  gemm_kernel<true><<<dim3(PROJ_GRID_X, PROJ_GRID_Y, NB), 256>>>(
      proj_w, CP, x, proj_b, nullptr);
  // 2) GN stats + affine fold
  stats_kernel<<<4, 256>>>();
  affine_kernel<<<3, 256>>>(gn_gamma, gn_beta);
  // 3) three attention branches
  attn_kernel<4, 2, 30, 15><<<dim3(NB*48*48, 2), 256, SM0>>>(0, scale_w, out + OFF_A0);
  attn_kernel<8, 4, 15,  3><<<dim3(NB*24*24, 4), 256, SM1>>>(1, scale_w, out + OFF_A1);
  attn_kernel<12,6, 10,  1><<<dim3(NB*16*16, 6), 256, SM2>>>(2, scale_w, out + OFF_A2);
  // 4) fuse GEMM -> y
  gemm_kernel<false><<<dim3(PROJ_GRID_X, 2, NB), 256>>>(
      fuse_w, CIN, nullptr, fuse_b, out);
}

// round 10
// speedup vs baseline: 1.1451x; 1.1451x over previous
#include <cuda_runtime.h>
#include <math.h>

#define HW 192
#define NPIX (HW*HW)
#define NB 2
#define CIN 180
#define CP 360
#define KDIM 180
#define KP 192            // padded K (12 chunks of 16)
#define MP_PROJ 384       // padded M for proj (6 x 64)
#define MP_FUSE 192       // padded M for fuse (3 x 64)

#define GX 288
#define GY_PROJ 6
#define BLKS_B (GX*GY_PROJ)   // 1728 proj blocks per batch

// ---------------- scratch (static device globals; no allocation) ----------------
__device__ float g_xp[(size_t)NB*CP*NPIX];     // projected (pre-GN) features
__device__ float g_yf[(size_t)NB*CIN*NPIX];    // fused attention output
__device__ float g_part[NB*BLKS_B*4];
__device__ float g_stats[8];                   // [b][g] -> {mu, inv_std}
__device__ float g_affA[NB*CP];                // folded GN scale
__device__ float g_affB[NB*CP];                // folded GN bias
// pre-split tf32 weights, k-major padded: AT[k*MPAD + m]
__device__ float g_ATp_hi[KP*MP_PROJ], g_ATp_lo[KP*MP_PROJ];
__device__ float g_ATf_hi[KP*MP_FUSE], g_ATf_lo[KP*MP_FUSE];

// ---------------- tf32 helpers ----------------
__device__ __forceinline__ void split_tf32(float x, float& hi, float& lo){
  unsigned h; asm("cvt.rna.tf32.f32 %0, %1;" : "=r"(h) : "f"(x));
  float fh = __uint_as_float(h);
  float r = x - fh;
  unsigned l; asm("cvt.rna.tf32.f32 %0, %1;" : "=r"(l) : "f"(r));
  hi = fh; lo = __uint_as_float(l);
}

__device__ __forceinline__ void mma_tf32(float* c, const unsigned* a, const unsigned* b){
  asm volatile(
    "mma.sync.aligned.m16n8k8.row.col.f32.tf32.tf32.f32 "
    "{%0,%1,%2,%3}, {%4,%5,%6,%7}, {%8,%9}, {%0,%1,%2,%3};"
    : "+f"(c[0]), "+f"(c[1]), "+f"(c[2]), "+f"(c[3])
    : "r"(a[0]), "r"(a[1]), "r"(a[2]), "r"(a[3]), "r"(b[0]), "r"(b[1]));
}

// ---------------- weight pre-split (runs each replay; trivial cost) ----------------
__global__ void split_w_kernel(const float* __restrict__ Wp, const float* __restrict__ Wf)
{
  int i = blockIdx.x*256 + threadIdx.x;
  const int NP = KP*MP_PROJ;
  if (i < NP){
    int k = i / MP_PROJ, m = i - k*MP_PROJ;
    float v = (m < CP && k < KDIM) ? Wp[m*KDIM + k] : 0.f;
    float h, l; split_tf32(v, h, l);
    g_ATp_hi[i] = h; g_ATp_lo[i] = l;
  } else {
    int j = i - NP;
    if (j < KP*MP_FUSE){
      int k = j / MP_FUSE, m = j - k*MP_FUSE;
      float v = (m < CIN && k < KDIM) ? Wf[m*KDIM + k] : 0.f;
      float h, l; split_tf32(v, h, l);
      g_ATf_hi[j] = h; g_ATf_lo[j] = l;
    }
  }
}

// ---------------- TF32 GEMM: C[b] = W (MxK) @ X[b] (KxNPIX) + bias ----------------
// BM=64, BN=128, BK=16, 256 threads (8 warps as 2x4), warp tile 32x32.
// 3xTF32 split: C += Ah*Bh + Ah*Bl + Al*Bh  (near-fp32 accuracy).
// PROJ=true : X = input x, C = g_xp, also emit GroupNorm partial sums.
// PROJ=false: X = g_yf,    C = d_out (y).
template<bool PROJ>
__global__ void __launch_bounds__(256) gemm_tf32(const float* __restrict__ Xin,
                                                 const float* __restrict__ bias,
                                                 float* __restrict__ Cout)
{
  constexpr int MPAD = PROJ ? MP_PROJ : MP_FUSE;
  constexpr int M    = PROJ ? CP : CIN;
  const float* AThi = PROJ ? g_ATp_hi : g_ATf_hi;
  const float* ATlo = PROJ ? g_ATp_lo : g_ATf_lo;

  __shared__ float As_hi[16*72],  As_lo[16*72];     // [k][m], stride 72 -> conflict-free
  __shared__ float Bs_hi[16*136], Bs_lo[16*136];    // [k][n], stride 136 -> conflict-free
  __shared__ float red[1024];

  const int b = blockIdx.z;
  const float* X = PROJ ? (Xin + (size_t)b*KDIM*NPIX)
                        : (g_yf + (size_t)b*CIN*NPIX);
  float* C = PROJ ? (g_xp + (size_t)b*CP*NPIX)
                  : (Cout + (size_t)b*CIN*NPIX);

  const int tid  = threadIdx.x;
  const int lane = tid & 31, warp = tid >> 5;
  const int wm = warp >> 2, wn = warp & 3;          // 2 x 4 warp grid
  const int g  = lane >> 2, t = lane & 3;
  const int m0 = blockIdx.y*64, n0 = blockIdx.x*128;

  float Cf[2][4][4];
#pragma unroll
  for (int mi=0;mi<2;mi++)
#pragma unroll
    for (int ni=0;ni<4;ni++)
#pragma unroll
      for (int e=0;e<4;e++) Cf[mi][ni][e] = 0.f;

  for (int k0 = 0; k0 < KP; k0 += 16){
    // --- A tile (pre-split, zero-padded, coalesced in m) ---
#pragma unroll
    for (int l=0;l<4;l++){
      int idx = l*256 + tid;
      int kk = idx >> 6, m = idx & 63;
      int src = (k0+kk)*MPAD + m0 + m;
      As_hi[kk*72 + m] = AThi[src];
      As_lo[kk*72 + m] = ATlo[src];
    }
    // --- B tile (fp32 load, split on the fly, float4 both ways) ---
#pragma unroll
    for (int l=0;l<2;l++){
      int idx = l*256 + tid;
      int kk = idx >> 5, c4 = idx & 31;
      int gk = k0 + kk;
      float4 v = make_float4(0.f,0.f,0.f,0.f);
      if (gk < KDIM) v = *(const float4*)(X + (size_t)gk*NPIX + n0 + c4*4);
      float4 h4, l4;
      split_tf32(v.x, h4.x, l4.x); split_tf32(v.y, h4.y, l4.y);
      split_tf32(v.z, h4.z, l4.z); split_tf32(v.w, h4.w, l4.w);
      *(float4*)(Bs_hi + kk*136 + c4*4) = h4;
      *(float4*)(Bs_lo + kk*136 + c4*4) = l4;
    }
    __syncthreads();

#pragma unroll
    for (int ks=0; ks<2; ks++){
      const int kb = ks*8;
      unsigned Ah[2][4], Al[2][4], Bh[4][2], Bl[4][2];
#pragma unroll
      for (int mi=0;mi<2;mi++){
        int r = wm*32 + mi*16 + g;
        Ah[mi][0] = __float_as_uint(As_hi[(kb+t  )*72 + r    ]);
        Ah[mi][1] = __float_as_uint(As_hi[(kb+t  )*72 + r + 8]);
        Ah[mi][2] = __float_as_uint(As_hi[(kb+t+4)*72 + r    ]);
        Ah[mi][3] = __float_as_uint(As_hi[(kb+t+4)*72 + r + 8]);
        Al[mi][0] = __float_as_uint(As_lo[(kb+t  )*72 + r    ]);
        Al[mi][1] = __float_as_uint(As_lo[(kb+t  )*72 + r + 8]);
        Al[mi][2] = __float_as_uint(As_lo[(kb+t+4)*72 + r    ]);
        Al[mi][3] = __float_as_uint(As_lo[(kb+t+4)*72 + r + 8]);
      }
#pragma unroll
      for (int ni=0;ni<4;ni++){
        int c = wn*32 + ni*8 + g;
        Bh[ni][0] = __float_as_uint(Bs_hi[(kb+t  )*136 + c]);
        Bh[ni][1] = __float_as_uint(Bs_hi[(kb+t+4)*136 + c]);
        Bl[ni][0] = __float_as_uint(Bs_lo[(kb+t  )*136 + c]);
        Bl[ni][1] = __float_as_uint(Bs_lo[(kb+t+4)*136 + c]);
      }
#pragma unroll
      for (int mi=0;mi<2;mi++)
#pragma unroll
        for (int ni=0;ni<4;ni++){
          mma_tf32(Cf[mi][ni], Ah[mi], Bh[ni]);
          mma_tf32(Cf[mi][ni], Ah[mi], Bl[ni]);
          mma_tf32(Cf[mi][ni], Al[mi], Bh[ni]);
        }
    }
    __syncthreads();
  }

  // --- epilogue: bias add, store, GN partial sums (PROJ) ---
  float st0=0.f, st1=0.f, st2=0.f, st3=0.f;
#pragma unroll
  for (int mi=0;mi<2;mi++){
#pragma unroll
    for (int rs=0;rs<2;rs++){
      int gm = m0 + wm*32 + mi*16 + g + rs*8;
      if (gm < M){
        float bb = bias[gm];
        float* crow = C + (size_t)gm*NPIX + n0 + wn*32;
        float s = 0.f, q = 0.f;
#pragma unroll
        for (int ni=0;ni<4;ni++){
          float v0 = Cf[mi][ni][rs*2+0] + bb;
          float v1 = Cf[mi][ni][rs*2+1] + bb;
          *(float2*)(crow + ni*8 + 2*t) = make_float2(v0, v1);
          if (PROJ){ s += v0 + v1; q = fmaf(v0,v0,fmaf(v1,v1,q)); }
        }
        if (PROJ){
          if (gm < CIN){ st0 += s; st1 += q; } else { st2 += s; st3 += q; }
        }
      }
    }
  }
  if (PROJ){
    __syncthreads();
    red[tid] = st0; red[256+tid] = st1; red[512+tid] = st2; red[768+tid] = st3;
    __syncthreads();
    for (int o=128;o;o>>=1){
      if (tid < o){
        red[tid]     += red[tid+o];
        red[256+tid] += red[256+tid+o];
        red[512+tid] += red[512+tid+o];
        red[768+tid] += red[768+tid+o];
      }
      __syncthreads();
    }
    if (tid == 0){
      int bid = (blockIdx.z*gridDim.y + blockIdx.y)*gridDim.x + blockIdx.x;
      g_part[bid*4+0]=red[0];   g_part[bid*4+1]=red[256];
      g_part[bid*4+2]=red[512]; g_part[bid*4+3]=red[768];
    }
  }
}

// ---------------- GroupNorm stats: deterministic reduce of partials ----------------
__global__ void stats_kernel()
{
  const int bg = blockIdx.x;          // b*2 + g, 4 blocks
  const int b = bg >> 1, g = bg & 1;
  __shared__ float ss[256], sq[256];
  float s = 0.f, q = 0.f;
  for (int i = threadIdx.x; i < BLKS_B; i += 256){
    int bid = b*BLKS_B + i;
    s += g_part[bid*4 + g*2];
    q += g_part[bid*4 + g*2 + 1];
  }
  ss[threadIdx.x] = s; sq[threadIdx.x] = q;
  __syncthreads();
  for (int o=128;o;o>>=1){
    if (threadIdx.x < o){ ss[threadIdx.x]+=ss[threadIdx.x+o]; sq[threadIdx.x]+=sq[threadIdx.x+o]; }
    __syncthreads();
  }
  if (threadIdx.x == 0){
    const float N = 180.f * (float)NPIX;
    float mu  = ss[0] / N;
    float var = sq[0] / N - mu*mu;
    g_stats[bg*2]   = mu;
    g_stats[bg*2+1] = rsqrtf(var + 1e-5f);
  }
}

// Fold GN into per-(batch,channel) affine: xn = xp * A + B
__global__ void affine_kernel(const float* __restrict__ gamma, const float* __restrict__ beta)
{
  int i = blockIdx.x*256 + threadIdx.x;
  if (i < NB*CP){
    int c = i % CP, b = i / CP;
    int g = (c >= CIN) ? 1 : 0;
    float mu   = g_stats[(b*2+g)*2];
    float istd = g_stats[(b*2+g)*2+1];
    float a = istd * gamma[c];
    g_affA[i] = a;
    g_affB[i] = fmaf(-mu, a, beta[c]);
  }
}

// ---------------- windowed attention, one block per (window, head) ----------------
// The reference's "global token" path is an exact identity (softmax of selected
// rows == selected rows of softmax), so attn maps and outputs are plain local
// window attention. Writes softmax rows to attn_out (= d_out slice) and
// scale_w * (attn@V) directly into g_yf.
template<int WS, int HE, int CHN, int NCH>
__global__ void __launch_bounds__(256) attn_kernel(int branch,
                                                   const float* __restrict__ swp,
                                                   float* __restrict__ attn_out)
{
  constexpr int T    = WS*WS;
  constexpr int NWIN = HW/WS;
  constexpr int TPAD = T + 4;
  constexpr int CPC  = CHN / NCH;
  static_assert(CHN % NCH == 0, "chunking");

  extern __shared__ float sm[];
  float* qT = sm;                  // [CHN][T]  (already *he^-0.5, GN applied)
  float* vT = sm + CHN*T;          // [CHN][T]
  float* Am = sm + 2*CHN*T;        // [T][TPAD]
  __shared__ int pixs[T];

  const int w  = blockIdx.x;
  const int hh = blockIdx.y;
  const int b  = w / (NWIN*NWIN);
  const int r  = w - b*NWIN*NWIN;
  const int ih = r / NWIN, iw = r - ih*NWIN;
  const int tid = threadIdx.x;

  if (tid < T){
    int ty = tid / WS, tx = tid - ty*WS;
    int hs  = (ih*WS + ty - WS/2 + HW) % HW;   // roll(+ws/2) on H
    int wsr = (iw*WS + tx + WS/2) % HW;        // roll(-ws/2) on W
    pixs[tid] = hs*HW + wsr;                   // same pixel for gather & scatter
  }
  __syncthreads();

  const float qsc = (HE==2) ? 0.70710678f : (HE==4) ? 0.5f : 0.40824829f;
  const float* xp = g_xp + (size_t)b*CP*NPIX;
  const float* aA = g_affA + b*CP;
  const float* aB = g_affB + b*CP;
  const int cb = branch*120 + hh;             // q channel = cb + cc*HE ; v = +60

  // ---- load + GN-normalize Q,V ----
  for (int idx = tid; idx < CHN*T; idx += 256){
    int cc = idx / T, t = idx - cc*T;
    int pix = pixs[t];
    int Cq = cb + cc*HE;
    int Cv = Cq + 60;
    float q = xp[(size_t)Cq*NPIX + pix];
    float v = xp[(size_t)Cv*NPIX + pix];
    qT[idx] = fmaf(q, aA[Cq], aB[Cq]) * qsc;
    vT[idx] = fmaf(v, aA[Cv], aB[Cv]);
  }
  __syncthreads();

  // ---- S = (q_l)(q_l)^T  (4x4 register tiles) ----
  constexpr int NT4 = T/4;
  for (int tile = tid; tile < NT4*NT4; tile += 256){
    int tt = tile / NT4, ssi = tile - tt*NT4;
    int t0 = tt*4, s0 = ssi*4;
    float accv[4][4];
#pragma unroll
    for (int i=0;i<4;i++)
#pragma unroll
      for (int j=0;j<4;j++) accv[i][j] = 0.f;
#pragma unroll
    for (int c=0;c<CHN;c++){
      float4 qa = *(const float4*)(qT + c*T + t0);
      float4 qb = *(const float4*)(qT + c*T + s0);
      float qav[4] = {qa.x,qa.y,qa.z,qa.w};
      float qbv[4] = {qb.x,qb.y,qb.z,qb.w};
#pragma unroll
      for (int i=0;i<4;i++)
#pragma unroll
        for (int j=0;j<4;j++)
          accv[i][j] = fmaf(qav[i], qbv[j], accv[i][j]);
    }
#pragma unroll
    for (int i=0;i<4;i++)
      *(float4*)(Am + (t0+i)*TPAD + s0) =
          make_float4(accv[i][0],accv[i][1],accv[i][2],accv[i][3]);
  }
  __syncthreads();

  // ---- softmax per row + write attn map to global ----
  const int warp = tid >> 5, lane = tid & 31;
  for (int t = warp; t < T; t += 8){
    float* arow = Am + t*TPAD;
    float mx = -1e30f;
    for (int s=lane; s<T; s+=32) mx = fmaxf(mx, arow[s]);
#pragma unroll
    for (int o=16;o;o>>=1) mx = fmaxf(mx, __shfl_xor_sync(0xffffffffu, mx, o));
    float sum = 0.f;
    for (int s=lane; s<T; s+=32){ float e = __expf(arow[s]-mx); arow[s]=e; sum+=e; }
#pragma unroll
    for (int o=16;o;o>>=1) sum += __shfl_xor_sync(0xffffffffu, sum, o);
    float inv = 1.f/sum;
    float* grow = attn_out + (((size_t)w*HE + hh)*T + t)*T;
    for (int s=lane; s<T; s+=32){ float p = arow[s]*inv; arow[s]=p; grow[s]=p; }
  }
  __syncthreads();

  // ---- O = attn @ V, scatter scaled output into y_fused ----
  float sw = swp[branch];
  if (tid < T*NCH){
    int chunk = tid / T, t = tid - chunk*T;
    const float* arow = Am + t*TPAD;
    const float* vb = vT + chunk*CPC*T;
    float o[CPC];
#pragma unroll
    for (int c=0;c<CPC;c++) o[c] = 0.f;
    for (int s=0; s<T; s+=4){
      float4 a4 = *(const float4*)(arow + s);
#pragma unroll
      for (int c=0;c<CPC;c++){
        float4 v4 = *(const float4*)(vb + c*T + s);
        o[c] = fmaf(a4.x, v4.x, o[c]);
        o[c] = fmaf(a4.y, v4.y, o[c]);
        o[c] = fmaf(a4.z, v4.z, o[c]);
        o[c] = fmaf(a4.w, v4.w, o[c]);
      }
    }
    int pix = pixs[t];
    float* yb = g_yf + (size_t)b*CIN*NPIX;
#pragma unroll
    for (int c=0;c<CPC;c++){
      int cc = chunk*CPC + c;
      int Cy = branch*60 + cc*HE + hh;
      yb[(size_t)Cy*NPIX + pix] = sw * o[c];
    }
  }
}

// ---------------- launcher ----------------
extern "C" void kernel_launch(void* const* d_in, const int* in_sizes, int n_in,
                              void* d_out, int out_size)
{
  const float* x        = (const float*)d_in[0];
  const float* proj_w   = (const float*)d_in[1];
  const float* proj_b   = (const float*)d_in[2];
  const float* gn_gamma = (const float*)d_in[3];
  const float* gn_beta  = (const float*)d_in[4];
  // d_in[5] token_scores: provably unused (global path is identity)
  const float* scale_w  = (const float*)d_in[6];
  const float* fuse_w   = (const float*)d_in[7];
  const float* fuse_b   = (const float*)d_in[8];
  float* out = (float*)d_out;

  // d_out layout: y | atn0 | atn1 | atn2
  const size_t OFF_A0 = (size_t)NB*CIN*NPIX;
  const size_t OFF_A1 = OFF_A0 + (size_t)NB*48*48*2*16*16;
  const size_t OFF_A2 = OFF_A1 + (size_t)NB*24*24*4*64*64;

  const int SM0 = (2*30*16  + 16*20)  * 4;   //  5,120 B
  const int SM1 = (2*15*64  + 64*68)  * 4;   // 25,088 B
  const int SM2 = (2*10*144 + 144*148)* 4;   // 96,768 B
  cudaFuncSetAttribute(attn_kernel<12,6,10,1>,
                       cudaFuncAttributeMaxDynamicSharedMemorySize, SM2);

  // 0) pre-split weights into tf32 hi/lo (padded, k-major)
  int prep_n = KP*MP_PROJ + KP*MP_FUSE;
  split_w_kernel<<<(prep_n + 255)/256, 256>>>(proj_w, fuse_w);
  // 1) proj GEMM (tensor core) + GN partials
  gemm_tf32<true><<<dim3(GX, GY_PROJ, NB), 256>>>(x, proj_b, nullptr);
  // 2) GN stats + affine fold
  stats_kernel<<<4, 256>>>();
  affine_kernel<<<3, 256>>>(gn_gamma, gn_beta);
  // 3) three attention branches
  attn_kernel<4, 2, 30, 15><<<dim3(NB*48*48, 2), 256, SM0>>>(0, scale_w, out + OFF_A0);
  attn_kernel<8, 4, 15,  3><<<dim3(NB*24*24, 4), 256, SM1>>>(1, scale_w, out + OFF_A1);
  attn_kernel<12,6, 10,  1><<<dim3(NB*16*16, 6), 256, SM2>>>(2, scale_w, out + OFF_A2);
  // 4) fuse GEMM (tensor core) -> y
  gemm_tf32<false><<<dim3(GX, 3, NB), 256>>>(nullptr, fuse_b, out);
}